// round 2
// baseline (speedup 1.0000x reference)
#include <cuda_runtime.h>

// Problem constants (fixed by the dataset)
#define NN   100000
#define Hh   4
#define C0   16
#define C1   8
#define HC0  64
#define HC1  32
#define CIN  64
#define EDIM 16
#define NET  10
#define NEG  0.2f

// ---------------- scratch (static device globals; no allocation) -------------
__device__ float g_h0   [NN * HC0];
__device__ float g_agg0 [NN * HC0];
__device__ float g_h1   [NN * HC1];
__device__ float g_ssrc0[NN * Hh];
__device__ float g_sdst0[NN * Hh];
__device__ float g_denom0[NN * Hh];
__device__ float g_ssrc1[NN * Hh];
__device__ float g_sdst1[NN * Hh];
__device__ float g_denom1[NN * Hh];
__device__ float g_etab [2][(NET + 1) * Hh];   // [layer][type*H + head], type==NET -> self-loop (mean attr)

__device__ __forceinline__ float leaky(float a) {
    return fmaxf(a, 0.f) + NEG * fminf(a, 0.f);
}

__device__ __forceinline__ void red_add_v4(float* p, float x, float y, float z, float w) {
    asm volatile("red.global.add.v4.f32 [%0], {%1,%2,%3,%4};"
                 :: "l"(p), "f"(x), "f"(y), "f"(z), "f"(w) : "memory");
}

// ---------------- edge-type attention table ---------------------------------
// etab[l][t][h] = sum_c ( (attr_t @ lin_e_w^T)[h*C+c] * att_e[h*C+c] )
__global__ void k_etab(const float* __restrict__ emb,
                       const float* __restrict__ lew0, const float* __restrict__ ae0,
                       const float* __restrict__ lew1, const float* __restrict__ ae1) {
    int tid = threadIdx.x;
    if (tid >= 2 * (NET + 1) * Hh) return;
    int l = tid / ((NET + 1) * Hh);
    int r = tid % ((NET + 1) * Hh);
    int t = r / Hh, h = r % Hh;
    const float* lew = l ? lew1 : lew0;
    const float* ae  = l ? ae1  : ae0;
    int C = l ? C1 : C0;
    float attr[EDIM];
    if (t < NET) {
        for (int d = 0; d < EDIM; d++) attr[d] = emb[t * EDIM + d];
    } else {
        for (int d = 0; d < EDIM; d++) {
            float s = 0.f;
            for (int u = 0; u < NET; u++) s += emb[u * EDIM + d];
            attr[d] = s / (float)NET;
        }
    }
    float val = 0.f;
    for (int c = 0; c < C; c++) {
        float e = 0.f;
        for (int d = 0; d < EDIM; d++) e += attr[d] * lew[(h * C + c) * EDIM + d];
        val += e * ae[h * C + c];
    }
    g_etab[l][t * Hh + h] = val;
}

// ---------------- node transform: h = x @ W^T, s_src/s_dst ------------------
// LAYER=1 reads g_agg0 with relu(.+bias0) applied on the fly.
template <int LAYER>
__global__ void k_node(const float* __restrict__ xin, const float* __restrict__ bias_in,
                       const float* __restrict__ W,
                       const float* __restrict__ asrc, const float* __restrict__ adst) {
    constexpr int HC = LAYER ? HC1 : HC0;
    constexpr int C  = LAYER ? C1  : C0;
    constexpr int NB = 256 / HC;               // nodes per block (4 or 8); NN divisible by both
    float* hbuf = LAYER ? g_h1    : g_h0;
    float* ssrc = LAYER ? g_ssrc1 : g_ssrc0;
    float* sdst = LAYER ? g_sdst1 : g_sdst0;
    const float* xr = LAYER ? (const float*)g_agg0 : xin;

    __shared__ float Wt[CIN * HC];             // Wt[k*HC + o]
    __shared__ float xs[NB * CIN];
    int tid = threadIdx.x;
    for (int i = tid; i < CIN * HC; i += 256) {
        int o = i / CIN, k = i % CIN;
        Wt[k * HC + o] = W[i];
    }
    int n0 = blockIdx.x * NB;
    for (int i = tid; i < NB * CIN; i += 256) {
        int j = i / CIN, k = i % CIN;
        float v = xr[(n0 + j) * CIN + k];
        if (LAYER) v = fmaxf(v + bias_in[k], 0.f);   // relu(prev_out + bias0)
        xs[i] = v;
    }
    __syncthreads();

    int j = tid / HC, o = tid % HC;
    int n = n0 + j;
    float acc = 0.f;
#pragma unroll
    for (int k = 0; k < CIN; k++) acc += xs[j * CIN + k] * Wt[k * HC + o];
    hbuf[n * HC + o] = acc;

    float ps = acc * asrc[o];
    float pd = acc * adst[o];
#pragma unroll
    for (int off = C / 2; off; off >>= 1) {
        ps += __shfl_down_sync(0xffffffffu, ps, off, C);
        pd += __shfl_down_sync(0xffffffffu, pd, off, C);
    }
    if ((o & (C - 1)) == 0) {
        ssrc[n * Hh + o / C] = ps;
        sdst[n * Hh + o / C] = pd;
    }
}

// ---------------- denom init: self-loop contribution -------------------------
template <int LAYER>
__global__ void k_denom_init() {
    const float* ssrc = LAYER ? g_ssrc1 : g_ssrc0;
    const float* sdst = LAYER ? g_sdst1 : g_sdst0;
    float* denom      = LAYER ? g_denom1 : g_denom0;
    int i = blockIdx.x * blockDim.x + threadIdx.x;
    if (i >= NN * Hh) return;
    int h = i & (Hh - 1);
    denom[i] = __expf(leaky(ssrc[i] + sdst[i] + g_etab[LAYER][NET * Hh + h]));
}

// ---------------- edge pass 1: denom[dst] += exp(leaky(alpha)) ---------------
template <int LAYER>
__global__ void k_edge_p1(const int* __restrict__ ei, const int* __restrict__ et, int E) {
    const float* ssrc = LAYER ? g_ssrc1 : g_ssrc0;
    const float* sdst = LAYER ? g_sdst1 : g_sdst0;
    float* denom      = LAYER ? g_denom1 : g_denom0;
    int e = blockIdx.x * blockDim.x + threadIdx.x;
    if (e >= E) return;
    int s = ei[e], d = ei[E + e], t = et[e];
    float4 a = *(const float4*)(ssrc + s * Hh);
    float4 b = *(const float4*)(sdst + d * Hh);
    const float* tb = &g_etab[LAYER][t * Hh];
    float e0 = __expf(leaky(a.x + b.x + tb[0]));
    float e1 = __expf(leaky(a.y + b.y + tb[1]));
    float e2 = __expf(leaky(a.z + b.z + tb[2]));
    float e3 = __expf(leaky(a.w + b.w + tb[3]));
    red_add_v4(denom + d * Hh, e0, e1, e2, e3);
}

// ---------------- self-loop aggregate init -----------------------------------
// LAYER=0: g_agg0[n] = h0[n] * w_loop
// LAYER=1: out[n]    = bias1 + h1[n] * w_loop
template <int LAYER>
__global__ void k_selfloop_init(const float* __restrict__ bias, float* __restrict__ out) {
    constexpr int HC = LAYER ? HC1 : HC0;
    constexpr int C  = LAYER ? C1  : C0;
    const float* hbuf  = LAYER ? g_h1    : g_h0;
    const float* ssrc  = LAYER ? g_ssrc1 : g_ssrc0;
    const float* sdst  = LAYER ? g_sdst1 : g_sdst0;
    const float* denom = LAYER ? g_denom1 : g_denom0;
    float* dst = LAYER ? out : g_agg0;
    int i = blockIdx.x * blockDim.x + threadIdx.x;
    if (i >= NN * HC) return;
    int n = i / HC, o = i % HC, h = o / C;
    float ex = __expf(leaky(ssrc[n * Hh + h] + sdst[n * Hh + h] + g_etab[LAYER][NET * Hh + h]));
    float v = hbuf[i] * __fdividef(ex, denom[n * Hh + h]);
    if (LAYER) v += bias[o];
    dst[i] = v;
}

// ---------------- edge pass 2: agg[dst] += h[src] * w ------------------------
template <int LAYER>
__global__ void k_edge_p2(const int* __restrict__ ei, const int* __restrict__ et, int E,
                          float* __restrict__ out) {
    constexpr int HC  = LAYER ? HC1 : HC0;
    constexpr int C   = LAYER ? C1  : C0;
    constexpr int TPE = HC / 4;                 // threads per edge (16 or 8)
    const float* ssrc  = LAYER ? g_ssrc1 : g_ssrc0;
    const float* sdst  = LAYER ? g_sdst1 : g_sdst0;
    const float* denom = LAYER ? g_denom1 : g_denom0;
    const float* hbuf  = LAYER ? g_h1    : g_h0;
    float* agg = LAYER ? out : g_agg0;

    unsigned gid = blockIdx.x * blockDim.x + threadIdx.x;
    unsigned e = gid / TPE;
    if (e >= (unsigned)E) return;
    int j = gid % TPE;
    int s = ei[e], d = ei[E + e], t = et[e];
    int h = (4 * j) / C;
    float alpha = leaky(ssrc[s * Hh + h] + sdst[d * Hh + h] + g_etab[LAYER][t * Hh + h]);
    float w = __fdividef(__expf(alpha), denom[d * Hh + h]);
    float4 hv = *(const float4*)(hbuf + s * HC + 4 * j);
    red_add_v4(agg + d * HC + 4 * j, hv.x * w, hv.y * w, hv.z * w, hv.w * w);
}

// -----------------------------------------------------------------------------
extern "C" void kernel_launch(void* const* d_in, const int* in_sizes, int n_in,
                              void* d_out, int out_size) {
    const float* x    = (const float*)d_in[0];
    const int*   ei   = (const int*)  d_in[1];
    const int*   et   = (const int*)  d_in[2];
    const float* emb  = (const float*)d_in[3];
    const float* w0   = (const float*)d_in[4];
    const float* as0  = (const float*)d_in[5];
    const float* ad0  = (const float*)d_in[6];
    const float* lew0 = (const float*)d_in[7];
    const float* ae0  = (const float*)d_in[8];
    const float* b0   = (const float*)d_in[9];
    const float* w1   = (const float*)d_in[10];
    const float* as1  = (const float*)d_in[11];
    const float* ad1  = (const float*)d_in[12];
    const float* lew1 = (const float*)d_in[13];
    const float* ae1  = (const float*)d_in[14];
    const float* b1   = (const float*)d_in[15];
    float* out = (float*)d_out;
    int E = in_sizes[1] / 2;

    const int TPB = 256;
    // edge-type attention tables (both layers)
    k_etab<<<1, 96>>>(emb, lew0, ae0, lew1, ae1);

    // ---- layer 0 ----
    k_node<0><<<NN / (256 / HC0), TPB>>>(x, nullptr, w0, as0, ad0);
    k_denom_init<0><<<(NN * Hh + TPB - 1) / TPB, TPB>>>();
    k_edge_p1<0><<<(E + TPB - 1) / TPB, TPB>>>(ei, et, E);
    k_selfloop_init<0><<<(NN * HC0 + TPB - 1) / TPB, TPB>>>(nullptr, nullptr);
    k_edge_p2<0><<<(E * (HC0 / 4) + TPB - 1) / TPB, TPB>>>(ei, et, E, nullptr);

    // ---- layer 1 (input = relu(agg0 + bias0), applied inside k_node<1>) ----
    k_node<1><<<NN / (256 / HC1), TPB>>>(nullptr, b0, w1, as1, ad1);
    k_denom_init<1><<<(NN * Hh + TPB - 1) / TPB, TPB>>>();
    k_edge_p1<1><<<(E + TPB - 1) / TPB, TPB>>>(ei, et, E);
    k_selfloop_init<1><<<(NN * HC1 + TPB - 1) / TPB, TPB>>>(b1, out);
    k_edge_p2<1><<<(E * (HC1 / 4) + TPB - 1) / TPB, TPB>>>(ei, et, E, out);
}